// round 13
// baseline (speedup 1.0000x reference)
#include <cuda_runtime.h>

#define DIMS   1024
#define NSTEPS 16384

// ---------------------------------------------------------------------------
// Scratch (device globals — no cudaMalloc allowed)
// ---------------------------------------------------------------------------
// g_h: double-buffered hidden state. Each element is an 8-byte atom:
//      high 32 bits = step tag, low 32 bits = float bits of h value.
//      Buffer (t & 1) holds h_t with tag (t + 1).  Tags are strictly
//      monotone per slot, so a reader checks freshness with a single
//      64-bit compare (p >= tag<<32) on a relaxed load — no fences.
__device__ unsigned long long g_h[2][DIMS];
// xi = inputs @ W_hi^T + b, precomputed for all timesteps (64 MB)
__device__ float g_xi[(size_t)NSTEPS * DIMS];

// ---------------------------------------------------------------------------
// Init: publish h0 with tag 1 into buffer 0, invalidate buffer 1.
// Re-run on every graph replay -> deterministic.
// ---------------------------------------------------------------------------
__global__ void rnn_init(const float* __restrict__ h0) {
    int i = threadIdx.x;
    g_h[0][i] = (1ull << 32) | (unsigned long long)__float_as_uint(h0[i]);
    g_h[1][i] = 0ull;
}

// ---------------------------------------------------------------------------
// xi GEMM: C[t,i] = sum_k A[t,k] * W[i,k] + b[i]
// 128x128 block tile, BK=16, 256 threads, 8x8 microtile per thread.
// Both operands are K-contiguous (NT layout) -> clean float4 global loads.
// ---------------------------------------------------------------------------
__global__ __launch_bounds__(256, 2) void xi_gemm(const float* __restrict__ A,
                                                  const float* __restrict__ W,
                                                  const float* __restrict__ bias) {
    __shared__ __align__(16) float As[16][132];  // [k][m], padded vs bank conflicts
    __shared__ __align__(16) float Bs[16][132];  // [k][n]

    const int tid = threadIdx.x;
    const int bm = blockIdx.x * 128;   // over timesteps
    const int bn = blockIdx.y * 128;   // over output dims
    const int lr = tid >> 2;           // 0..63  (load row)
    const int lc = (tid & 3) << 2;     // 0,4,8,12 (load col within k-chunk)
    const int tm = (tid & 15) << 3;    // microtile row base
    const int tn = (tid >> 4) << 3;    // microtile col base

    float acc[8][8];
#pragma unroll
    for (int i = 0; i < 8; i++)
#pragma unroll
        for (int j = 0; j < 8; j++) acc[i][j] = 0.f;

    for (int k0 = 0; k0 < DIMS; k0 += 16) {
        float4 a0 = *(const float4*)(A + (size_t)(bm + lr) * DIMS + k0 + lc);
        float4 a1 = *(const float4*)(A + (size_t)(bm + lr + 64) * DIMS + k0 + lc);
        float4 b0 = *(const float4*)(W + (size_t)(bn + lr) * DIMS + k0 + lc);
        float4 b1 = *(const float4*)(W + (size_t)(bn + lr + 64) * DIMS + k0 + lc);
        __syncthreads();  // protect previous iteration's reads
        As[lc + 0][lr] = a0.x;  As[lc + 1][lr] = a0.y;
        As[lc + 2][lr] = a0.z;  As[lc + 3][lr] = a0.w;
        As[lc + 0][lr + 64] = a1.x;  As[lc + 1][lr + 64] = a1.y;
        As[lc + 2][lr + 64] = a1.z;  As[lc + 3][lr + 64] = a1.w;
        Bs[lc + 0][lr] = b0.x;  Bs[lc + 1][lr] = b0.y;
        Bs[lc + 2][lr] = b0.z;  Bs[lc + 3][lr] = b0.w;
        Bs[lc + 0][lr + 64] = b1.x;  Bs[lc + 1][lr + 64] = b1.y;
        Bs[lc + 2][lr + 64] = b1.z;  Bs[lc + 3][lr + 64] = b1.w;
        __syncthreads();
#pragma unroll
        for (int kk = 0; kk < 16; kk++) {
            float4 xa0 = *(const float4*)&As[kk][tm];
            float4 xa1 = *(const float4*)&As[kk][tm + 4];
            float4 xb0 = *(const float4*)&Bs[kk][tn];
            float4 xb1 = *(const float4*)&Bs[kk][tn + 4];
            float ar[8] = {xa0.x, xa0.y, xa0.z, xa0.w, xa1.x, xa1.y, xa1.z, xa1.w};
            float br[8] = {xb0.x, xb0.y, xb0.z, xb0.w, xb1.x, xb1.y, xb1.z, xb1.w};
#pragma unroll
            for (int i = 0; i < 8; i++)
#pragma unroll
                for (int j = 0; j < 8; j++)
                    acc[i][j] = fmaf(ar[i], br[j], acc[i][j]);
        }
    }

    float4 bv0 = *(const float4*)(bias + bn + tn);
    float4 bv1 = *(const float4*)(bias + bn + tn + 4);
    float bb[8] = {bv0.x, bv0.y, bv0.z, bv0.w, bv1.x, bv1.y, bv1.z, bv1.w};
#pragma unroll
    for (int i = 0; i < 8; i++) {
        float4 o0 = make_float4(acc[i][0] + bb[0], acc[i][1] + bb[1],
                                acc[i][2] + bb[2], acc[i][3] + bb[3]);
        float4 o1 = make_float4(acc[i][4] + bb[4], acc[i][5] + bb[5],
                                acc[i][6] + bb[6], acc[i][7] + bb[7]);
        float* dst = g_xi + (size_t)(bm + tm + i) * DIMS + bn + tn;
        *(float4*)dst       = o0;
        *(float4*)(dst + 4) = o1;
    }
}

// ---------------------------------------------------------------------------
// Sequential scan: 64 persistent blocks x 128 threads.
// Block owns 16 rows of W_hh (4 rows per warp), entirely in REGISTERS
// (32 floats x 4 rows per lane; lane covers columns {lane + 32k}).
// Per step: spin on 32 tagged b64 loads (coalesced), 128 FFMA, butterfly
// reduce, 4 lanes finalize (tanh + publish tagged h + residual output).
// ---------------------------------------------------------------------------
__global__ __launch_bounds__(128, 1) void rnn_scan(const float* __restrict__ inputs,
                                                   const float* __restrict__ Whh,
                                                   float* __restrict__ out) {
    const int lane = threadIdx.x & 31;
    const int warp = threadIdx.x >> 5;
    const int rowbase = blockIdx.x * 16 + warp * 4;

    // One-time: load this lane's W_hh slice into registers (128 regs)
    float w0[32], w1[32], w2[32], w3[32];
#pragma unroll
    for (int k = 0; k < 32; k++) {
        int c = lane + (k << 5);
        w0[k] = Whh[(size_t)(rowbase + 0) * DIMS + c];
        w1[k] = Whh[(size_t)(rowbase + 1) * DIMS + c];
        w2[k] = Whh[(size_t)(rowbase + 2) * DIMS + c];
        w3[k] = Whh[(size_t)(rowbase + 3) * DIMS + c];
    }

    const bool fin = (lane < 4);
    const int myrow = rowbase + (lane & 3);

    for (int t = 0; t < NSTEPS; t++) {
        // Prefetch per-step scalars (independent of h -> hides under spin)
        float xiv = 0.f, inv = 0.f;
        if (fin) {
            xiv = __ldg(&g_xi[(size_t)t * DIMS + myrow]);
            inv = __ldg(&inputs[(size_t)t * DIMS + myrow]);
        }

        const unsigned long long* src = g_h[t & 1];
        const unsigned long long thresh =
            ((unsigned long long)(unsigned)(t + 1)) << 32;

        // Spin until all 32 of this lane's tagged values carry tag t+1.
        // Tag monotonicity makes a single u64 >= compare sufficient.
        float v[32];
        for (;;) {
            bool ok = true;
#pragma unroll
            for (int k = 0; k < 32; k++) {
                unsigned long long p;
                asm volatile("ld.relaxed.gpu.global.u64 %0, [%1];"
                             : "=l"(p)
                             : "l"(src + lane + (k << 5)));
                v[k] = __uint_as_float((unsigned int)p);
                ok = ok && (p >= thresh);
            }
            if (__all_sync(0xffffffffu, ok)) break;
        }

        // 4 rows x 32 columns of partial dot products per lane
        float a0 = 0.f, a1 = 0.f, a2 = 0.f, a3 = 0.f;
#pragma unroll
        for (int k = 0; k < 32; k++) {
            a0 = fmaf(v[k], w0[k], a0);
            a1 = fmaf(v[k], w1[k], a1);
            a2 = fmaf(v[k], w2[k], a2);
            a3 = fmaf(v[k], w3[k], a3);
        }

        // Butterfly reduce across the warp (all lanes end with full sums)
#pragma unroll
        for (int off = 16; off; off >>= 1) {
            a0 += __shfl_xor_sync(0xffffffffu, a0, off);
            a1 += __shfl_xor_sync(0xffffffffu, a1, off);
            a2 += __shfl_xor_sync(0xffffffffu, a2, off);
            a3 += __shfl_xor_sync(0xffffffffu, a3, off);
        }

        if (fin) {
            float s = (lane == 0) ? a0 : (lane == 1) ? a1 : (lane == 2) ? a2 : a3;
            float hn = tanhf(xiv + s);
            unsigned long long pk =
                (((unsigned long long)(unsigned)(t + 2)) << 32) |
                (unsigned long long)__float_as_uint(hn);
            asm volatile("st.relaxed.gpu.global.u64 [%0], %1;"
                         :: "l"(&g_h[(t + 1) & 1][myrow]), "l"(pk)
                         : "memory");
            out[(size_t)t * DIMS + myrow] = hn + inv;
        }
    }
}

// ---------------------------------------------------------------------------
// Launch: init -> GEMM -> scan, all on the capture stream, no sync, no alloc.
// ---------------------------------------------------------------------------
extern "C" void kernel_launch(void* const* d_in, const int* in_sizes, int n_in,
                              void* d_out, int out_size) {
    const float* inputs = (const float*)d_in[0];
    const float* h0     = (const float*)d_in[1];
    const float* W_hi   = (const float*)d_in[2];
    const float* W_hh   = (const float*)d_in[3];
    const float* b      = (const float*)d_in[4];
    float* out = (float*)d_out;

    rnn_init<<<1, DIMS>>>(h0);

    dim3 grid(NSTEPS / 128, DIMS / 128);
    xi_gemm<<<grid, 256>>>(inputs, W_hi, b);

    // 64 blocks < 148 SMs, 1 block/SM guaranteed by __launch_bounds__(128,1):
    // all blocks co-resident -> the cross-block spin protocol cannot deadlock.
    rnn_scan<<<64, 128>>>(inputs, W_hh, out);
}

// round 14
// speedup vs baseline: 1.0022x; 1.0022x over previous
#include <cuda_runtime.h>

#define DIMS   1024
#define NSTEPS 16384

// ---------------------------------------------------------------------------
// Scratch (device globals — no cudaMalloc allowed)
// ---------------------------------------------------------------------------
// g_h: double-buffered hidden state. Each element is an 8-byte atom:
//      high 32 bits = step tag, low 32 bits = float bits of h value.
//      Buffer (t & 1) holds h_t with tag (t + 1).  Tags are strictly
//      monotone per slot, so a reader checks freshness with a single
//      64-bit compare (p >= tag<<32) on a relaxed load — no fences.
__device__ unsigned long long g_h[2][DIMS];
// xi = inputs @ W_hi^T + b, precomputed for all timesteps (64 MB)
__device__ float g_xi[(size_t)NSTEPS * DIMS];

// ---------------------------------------------------------------------------
// Init: publish h0 with tag 1 into buffer 0, invalidate buffer 1.
// Re-run on every graph replay -> deterministic.
// ---------------------------------------------------------------------------
__global__ void rnn_init(const float* __restrict__ h0) {
    int i = threadIdx.x;
    g_h[0][i] = (1ull << 32) | (unsigned long long)__float_as_uint(h0[i]);
    g_h[1][i] = 0ull;
}

// ---------------------------------------------------------------------------
// xi GEMM: C[t,i] = sum_k A[t,k] * W[i,k] + b[i]
// 128x128 block tile, BK=16, 256 threads, 8x8 microtile per thread.
// Both operands are K-contiguous (NT layout) -> clean float4 global loads.
// ---------------------------------------------------------------------------
__global__ __launch_bounds__(256, 2) void xi_gemm(const float* __restrict__ A,
                                                  const float* __restrict__ W,
                                                  const float* __restrict__ bias) {
    __shared__ __align__(16) float As[16][132];  // [k][m], padded vs bank conflicts
    __shared__ __align__(16) float Bs[16][132];  // [k][n]

    const int tid = threadIdx.x;
    const int bm = blockIdx.x * 128;   // over timesteps
    const int bn = blockIdx.y * 128;   // over output dims
    const int lr = tid >> 2;           // 0..63  (load row)
    const int lc = (tid & 3) << 2;     // 0,4,8,12 (load col within k-chunk)
    const int tm = (tid & 15) << 3;    // microtile row base
    const int tn = (tid >> 4) << 3;    // microtile col base

    float acc[8][8];
#pragma unroll
    for (int i = 0; i < 8; i++)
#pragma unroll
        for (int j = 0; j < 8; j++) acc[i][j] = 0.f;

    for (int k0 = 0; k0 < DIMS; k0 += 16) {
        float4 a0 = *(const float4*)(A + (size_t)(bm + lr) * DIMS + k0 + lc);
        float4 a1 = *(const float4*)(A + (size_t)(bm + lr + 64) * DIMS + k0 + lc);
        float4 b0 = *(const float4*)(W + (size_t)(bn + lr) * DIMS + k0 + lc);
        float4 b1 = *(const float4*)(W + (size_t)(bn + lr + 64) * DIMS + k0 + lc);
        __syncthreads();  // protect previous iteration's reads
        As[lc + 0][lr] = a0.x;  As[lc + 1][lr] = a0.y;
        As[lc + 2][lr] = a0.z;  As[lc + 3][lr] = a0.w;
        As[lc + 0][lr + 64] = a1.x;  As[lc + 1][lr + 64] = a1.y;
        As[lc + 2][lr + 64] = a1.z;  As[lc + 3][lr + 64] = a1.w;
        Bs[lc + 0][lr] = b0.x;  Bs[lc + 1][lr] = b0.y;
        Bs[lc + 2][lr] = b0.z;  Bs[lc + 3][lr] = b0.w;
        Bs[lc + 0][lr + 64] = b1.x;  Bs[lc + 1][lr + 64] = b1.y;
        Bs[lc + 2][lr + 64] = b1.z;  Bs[lc + 3][lr + 64] = b1.w;
        __syncthreads();
#pragma unroll
        for (int kk = 0; kk < 16; kk++) {
            float4 xa0 = *(const float4*)&As[kk][tm];
            float4 xa1 = *(const float4*)&As[kk][tm + 4];
            float4 xb0 = *(const float4*)&Bs[kk][tn];
            float4 xb1 = *(const float4*)&Bs[kk][tn + 4];
            float ar[8] = {xa0.x, xa0.y, xa0.z, xa0.w, xa1.x, xa1.y, xa1.z, xa1.w};
            float br[8] = {xb0.x, xb0.y, xb0.z, xb0.w, xb1.x, xb1.y, xb1.z, xb1.w};
#pragma unroll
            for (int i = 0; i < 8; i++)
#pragma unroll
                for (int j = 0; j < 8; j++)
                    acc[i][j] = fmaf(ar[i], br[j], acc[i][j]);
        }
    }

    float4 bv0 = *(const float4*)(bias + bn + tn);
    float4 bv1 = *(const float4*)(bias + bn + tn + 4);
    float bb[8] = {bv0.x, bv0.y, bv0.z, bv0.w, bv1.x, bv1.y, bv1.z, bv1.w};
#pragma unroll
    for (int i = 0; i < 8; i++) {
        float4 o0 = make_float4(acc[i][0] + bb[0], acc[i][1] + bb[1],
                                acc[i][2] + bb[2], acc[i][3] + bb[3]);
        float4 o1 = make_float4(acc[i][4] + bb[4], acc[i][5] + bb[5],
                                acc[i][6] + bb[6], acc[i][7] + bb[7]);
        float* dst = g_xi + (size_t)(bm + tm + i) * DIMS + bn + tn;
        *(float4*)dst       = o0;
        *(float4*)(dst + 4) = o1;
    }
}

// ---------------------------------------------------------------------------
// Sequential scan: 64 persistent blocks x 128 threads.
// Block owns 16 rows of W_hh (4 rows per warp), entirely in REGISTERS
// (32 floats x 4 rows per lane; lane covers columns {lane + 32k}).
// Per step: spin on 32 tagged b64 loads (coalesced), 128 FFMA, butterfly
// reduce, 4 lanes finalize (tanh + publish tagged h + residual output).
// ---------------------------------------------------------------------------
__global__ __launch_bounds__(128, 1) void rnn_scan(const float* __restrict__ inputs,
                                                   const float* __restrict__ Whh,
                                                   float* __restrict__ out) {
    const int lane = threadIdx.x & 31;
    const int warp = threadIdx.x >> 5;
    const int rowbase = blockIdx.x * 16 + warp * 4;

    // One-time: load this lane's W_hh slice into registers (128 regs)
    float w0[32], w1[32], w2[32], w3[32];
#pragma unroll
    for (int k = 0; k < 32; k++) {
        int c = lane + (k << 5);
        w0[k] = Whh[(size_t)(rowbase + 0) * DIMS + c];
        w1[k] = Whh[(size_t)(rowbase + 1) * DIMS + c];
        w2[k] = Whh[(size_t)(rowbase + 2) * DIMS + c];
        w3[k] = Whh[(size_t)(rowbase + 3) * DIMS + c];
    }

    const bool fin = (lane < 4);
    const int myrow = rowbase + (lane & 3);

    for (int t = 0; t < NSTEPS; t++) {
        // Prefetch per-step scalars (independent of h -> hides under spin)
        float xiv = 0.f, inv = 0.f;
        if (fin) {
            xiv = __ldg(&g_xi[(size_t)t * DIMS + myrow]);
            inv = __ldg(&inputs[(size_t)t * DIMS + myrow]);
        }

        const unsigned long long* src = g_h[t & 1];
        const unsigned long long thresh =
            ((unsigned long long)(unsigned)(t + 1)) << 32;

        // Spin until all 32 of this lane's tagged values carry tag t+1.
        // Tag monotonicity makes a single u64 >= compare sufficient.
        float v[32];
        for (;;) {
            bool ok = true;
#pragma unroll
            for (int k = 0; k < 32; k++) {
                unsigned long long p;
                asm volatile("ld.relaxed.gpu.global.u64 %0, [%1];"
                             : "=l"(p)
                             : "l"(src + lane + (k << 5)));
                v[k] = __uint_as_float((unsigned int)p);
                ok = ok && (p >= thresh);
            }
            if (__all_sync(0xffffffffu, ok)) break;
        }

        // 4 rows x 32 columns of partial dot products per lane
        float a0 = 0.f, a1 = 0.f, a2 = 0.f, a3 = 0.f;
#pragma unroll
        for (int k = 0; k < 32; k++) {
            a0 = fmaf(v[k], w0[k], a0);
            a1 = fmaf(v[k], w1[k], a1);
            a2 = fmaf(v[k], w2[k], a2);
            a3 = fmaf(v[k], w3[k], a3);
        }

        // Butterfly reduce across the warp (all lanes end with full sums)
#pragma unroll
        for (int off = 16; off; off >>= 1) {
            a0 += __shfl_xor_sync(0xffffffffu, a0, off);
            a1 += __shfl_xor_sync(0xffffffffu, a1, off);
            a2 += __shfl_xor_sync(0xffffffffu, a2, off);
            a3 += __shfl_xor_sync(0xffffffffu, a3, off);
        }

        if (fin) {
            float s = (lane == 0) ? a0 : (lane == 1) ? a1 : (lane == 2) ? a2 : a3;
            float hn = tanhf(xiv + s);
            unsigned long long pk =
                (((unsigned long long)(unsigned)(t + 2)) << 32) |
                (unsigned long long)__float_as_uint(hn);
            asm volatile("st.relaxed.gpu.global.u64 [%0], %1;"
                         :: "l"(&g_h[(t + 1) & 1][myrow]), "l"(pk)
                         : "memory");
            out[(size_t)t * DIMS + myrow] = hn + inv;
        }
    }
}

// ---------------------------------------------------------------------------
// Launch: init -> GEMM -> scan, all on the capture stream, no sync, no alloc.
// ---------------------------------------------------------------------------
extern "C" void kernel_launch(void* const* d_in, const int* in_sizes, int n_in,
                              void* d_out, int out_size) {
    const float* inputs = (const float*)d_in[0];
    const float* h0     = (const float*)d_in[1];
    const float* W_hi   = (const float*)d_in[2];
    const float* W_hh   = (const float*)d_in[3];
    const float* b      = (const float*)d_in[4];
    float* out = (float*)d_out;

    rnn_init<<<1, DIMS>>>(h0);

    dim3 grid(NSTEPS / 128, DIMS / 128);
    xi_gemm<<<grid, 256>>>(inputs, W_hi, b);

    // 64 blocks < 148 SMs, 1 block/SM guaranteed by __launch_bounds__(128,1):
    // all blocks co-resident -> the cross-block spin protocol cannot deadlock.
    rnn_scan<<<64, 128>>>(inputs, W_hh, out);
}

// round 15
// speedup vs baseline: 1.0365x; 1.0342x over previous
#include <cuda_runtime.h>

#define DIMS   1024
#define NSTEPS 16384

// ---------------------------------------------------------------------------
// Scratch (device globals — no cudaMalloc allowed)
// ---------------------------------------------------------------------------
// g_h: double-buffered hidden state. Each element is an 8-byte atom:
//      high 32 bits = step tag, low 32 bits = float bits of h value.
//      Buffer (t & 1) holds h_t with tag (t + 1).  Tags are strictly
//      monotone per slot, so a reader checks freshness with a single
//      64-bit compare (p >= tag<<32) on a relaxed load — no fences.
__device__ unsigned long long g_h[2][DIMS];
// xi = inputs @ W_hi^T + b, precomputed for all timesteps (64 MB)
__device__ float g_xi[(size_t)NSTEPS * DIMS];

// ---------------------------------------------------------------------------
// Init: publish h0 with tag 1 into buffer 0, invalidate buffer 1.
// Re-run on every graph replay -> deterministic.
// ---------------------------------------------------------------------------
__global__ void rnn_init(const float* __restrict__ h0) {
    int i = threadIdx.x;
    g_h[0][i] = (1ull << 32) | (unsigned long long)__float_as_uint(h0[i]);
    g_h[1][i] = 0ull;
}

// ---------------------------------------------------------------------------
// xi GEMM: C[t,i] = sum_k A[t,k] * W[i,k] + b[i]
// 128x128 block tile, BK=16, 256 threads, 8x8 microtile per thread.
// Both operands are K-contiguous (NT layout) -> clean float4 global loads.
// ---------------------------------------------------------------------------
__global__ __launch_bounds__(256, 2) void xi_gemm(const float* __restrict__ A,
                                                  const float* __restrict__ W,
                                                  const float* __restrict__ bias) {
    __shared__ __align__(16) float As[16][132];  // [k][m], padded vs bank conflicts
    __shared__ __align__(16) float Bs[16][132];  // [k][n]

    const int tid = threadIdx.x;
    const int bm = blockIdx.x * 128;   // over timesteps
    const int bn = blockIdx.y * 128;   // over output dims
    const int lr = tid >> 2;           // 0..63  (load row)
    const int lc = (tid & 3) << 2;     // 0,4,8,12 (load col within k-chunk)
    const int tm = (tid & 15) << 3;    // microtile row base
    const int tn = (tid >> 4) << 3;    // microtile col base

    float acc[8][8];
#pragma unroll
    for (int i = 0; i < 8; i++)
#pragma unroll
        for (int j = 0; j < 8; j++) acc[i][j] = 0.f;

    for (int k0 = 0; k0 < DIMS; k0 += 16) {
        float4 a0 = *(const float4*)(A + (size_t)(bm + lr) * DIMS + k0 + lc);
        float4 a1 = *(const float4*)(A + (size_t)(bm + lr + 64) * DIMS + k0 + lc);
        float4 b0 = *(const float4*)(W + (size_t)(bn + lr) * DIMS + k0 + lc);
        float4 b1 = *(const float4*)(W + (size_t)(bn + lr + 64) * DIMS + k0 + lc);
        __syncthreads();  // protect previous iteration's reads
        As[lc + 0][lr] = a0.x;  As[lc + 1][lr] = a0.y;
        As[lc + 2][lr] = a0.z;  As[lc + 3][lr] = a0.w;
        As[lc + 0][lr + 64] = a1.x;  As[lc + 1][lr + 64] = a1.y;
        As[lc + 2][lr + 64] = a1.z;  As[lc + 3][lr + 64] = a1.w;
        Bs[lc + 0][lr] = b0.x;  Bs[lc + 1][lr] = b0.y;
        Bs[lc + 2][lr] = b0.z;  Bs[lc + 3][lr] = b0.w;
        Bs[lc + 0][lr + 64] = b1.x;  Bs[lc + 1][lr + 64] = b1.y;
        Bs[lc + 2][lr + 64] = b1.z;  Bs[lc + 3][lr + 64] = b1.w;
        __syncthreads();
#pragma unroll
        for (int kk = 0; kk < 16; kk++) {
            float4 xa0 = *(const float4*)&As[kk][tm];
            float4 xa1 = *(const float4*)&As[kk][tm + 4];
            float4 xb0 = *(const float4*)&Bs[kk][tn];
            float4 xb1 = *(const float4*)&Bs[kk][tn + 4];
            float ar[8] = {xa0.x, xa0.y, xa0.z, xa0.w, xa1.x, xa1.y, xa1.z, xa1.w};
            float br[8] = {xb0.x, xb0.y, xb0.z, xb0.w, xb1.x, xb1.y, xb1.z, xb1.w};
#pragma unroll
            for (int i = 0; i < 8; i++)
#pragma unroll
                for (int j = 0; j < 8; j++)
                    acc[i][j] = fmaf(ar[i], br[j], acc[i][j]);
        }
    }

    float4 bv0 = *(const float4*)(bias + bn + tn);
    float4 bv1 = *(const float4*)(bias + bn + tn + 4);
    float bb[8] = {bv0.x, bv0.y, bv0.z, bv0.w, bv1.x, bv1.y, bv1.z, bv1.w};
#pragma unroll
    for (int i = 0; i < 8; i++) {
        float4 o0 = make_float4(acc[i][0] + bb[0], acc[i][1] + bb[1],
                                acc[i][2] + bb[2], acc[i][3] + bb[3]);
        float4 o1 = make_float4(acc[i][4] + bb[4], acc[i][5] + bb[5],
                                acc[i][6] + bb[6], acc[i][7] + bb[7]);
        float* dst = g_xi + (size_t)(bm + tm + i) * DIMS + bn + tn;
        *(float4*)dst       = o0;
        *(float4*)(dst + 4) = o1;
    }
}

// ---------------------------------------------------------------------------
// Sequential scan: 64 persistent blocks x 128 threads.
// Block owns 16 rows of W_hh (4 rows per warp), entirely in REGISTERS
// (32 floats x 4 rows per lane; lane covers columns {lane + 32k}).
// Per step: spin on 32 tagged b64 loads (coalesced), 128 FFMA, butterfly
// reduce, 4 lanes finalize (tanh + publish tagged h + residual output).
// ---------------------------------------------------------------------------
__global__ __launch_bounds__(128, 1) void rnn_scan(const float* __restrict__ inputs,
                                                   const float* __restrict__ Whh,
                                                   float* __restrict__ out) {
    const int lane = threadIdx.x & 31;
    const int warp = threadIdx.x >> 5;
    const int rowbase = blockIdx.x * 16 + warp * 4;

    // One-time: load this lane's W_hh slice into registers (128 regs)
    float w0[32], w1[32], w2[32], w3[32];
#pragma unroll
    for (int k = 0; k < 32; k++) {
        int c = lane + (k << 5);
        w0[k] = Whh[(size_t)(rowbase + 0) * DIMS + c];
        w1[k] = Whh[(size_t)(rowbase + 1) * DIMS + c];
        w2[k] = Whh[(size_t)(rowbase + 2) * DIMS + c];
        w3[k] = Whh[(size_t)(rowbase + 3) * DIMS + c];
    }

    const bool fin = (lane < 4);
    const int myrow = rowbase + (lane & 3);

    for (int t = 0; t < NSTEPS; t++) {
        // Prefetch per-step scalars (independent of h -> hides under spin)
        float xiv = 0.f, inv = 0.f;
        if (fin) {
            xiv = __ldg(&g_xi[(size_t)t * DIMS + myrow]);
            inv = __ldg(&inputs[(size_t)t * DIMS + myrow]);
        }

        const unsigned long long* src = g_h[t & 1];
        const unsigned long long thresh =
            ((unsigned long long)(unsigned)(t + 1)) << 32;

        // Spin until all 32 of this lane's tagged values carry tag t+1.
        // Tag monotonicity makes a single u64 >= compare sufficient.
        float v[32];
        for (;;) {
            bool ok = true;
#pragma unroll
            for (int k = 0; k < 32; k++) {
                unsigned long long p;
                asm volatile("ld.relaxed.gpu.global.u64 %0, [%1];"
                             : "=l"(p)
                             : "l"(src + lane + (k << 5)));
                v[k] = __uint_as_float((unsigned int)p);
                ok = ok && (p >= thresh);
            }
            if (__all_sync(0xffffffffu, ok)) break;
        }

        // 4 rows x 32 columns of partial dot products per lane
        float a0 = 0.f, a1 = 0.f, a2 = 0.f, a3 = 0.f;
#pragma unroll
        for (int k = 0; k < 32; k++) {
            a0 = fmaf(v[k], w0[k], a0);
            a1 = fmaf(v[k], w1[k], a1);
            a2 = fmaf(v[k], w2[k], a2);
            a3 = fmaf(v[k], w3[k], a3);
        }

        // Butterfly reduce across the warp (all lanes end with full sums)
#pragma unroll
        for (int off = 16; off; off >>= 1) {
            a0 += __shfl_xor_sync(0xffffffffu, a0, off);
            a1 += __shfl_xor_sync(0xffffffffu, a1, off);
            a2 += __shfl_xor_sync(0xffffffffu, a2, off);
            a3 += __shfl_xor_sync(0xffffffffu, a3, off);
        }

        if (fin) {
            float s = (lane == 0) ? a0 : (lane == 1) ? a1 : (lane == 2) ? a2 : a3;
            float hn = tanhf(xiv + s);
            unsigned long long pk =
                (((unsigned long long)(unsigned)(t + 2)) << 32) |
                (unsigned long long)__float_as_uint(hn);
            asm volatile("st.relaxed.gpu.global.u64 [%0], %1;"
                         :: "l"(&g_h[(t + 1) & 1][myrow]), "l"(pk)
                         : "memory");
            out[(size_t)t * DIMS + myrow] = hn + inv;
        }
    }
}

// ---------------------------------------------------------------------------
// Launch: init -> GEMM -> scan, all on the capture stream, no sync, no alloc.
// ---------------------------------------------------------------------------
extern "C" void kernel_launch(void* const* d_in, const int* in_sizes, int n_in,
                              void* d_out, int out_size) {
    const float* inputs = (const float*)d_in[0];
    const float* h0     = (const float*)d_in[1];
    const float* W_hi   = (const float*)d_in[2];
    const float* W_hh   = (const float*)d_in[3];
    const float* b      = (const float*)d_in[4];
    float* out = (float*)d_out;

    rnn_init<<<1, DIMS>>>(h0);

    dim3 grid(NSTEPS / 128, DIMS / 128);
    xi_gemm<<<grid, 256>>>(inputs, W_hi, b);

    // 64 blocks < 148 SMs, 1 block/SM guaranteed by __launch_bounds__(128,1):
    // all blocks co-resident -> the cross-block spin protocol cannot deadlock.
    rnn_scan<<<64, 128>>>(inputs, W_hh, out);
}